// round 16
// baseline (speedup 1.0000x reference)
#include <cuda_runtime.h>
#include <cstdint>

// Problem constants (fixed shapes per reference)
#define NMAX   50000
#define EMAX   800000
#define IN_F   128
#define OUT_F  128
#define HEADS  8
#define HDIM   16   // OUT_F / HEADS
#define EDGE_F 32

typedef unsigned long long ull;

// ---------------------------------------------------------------------------
// Scratch (static device globals -- no runtime allocation allowed).
// ---------------------------------------------------------------------------
__device__ __align__(16) float g_QKV[NMAX * 384];     // per node: Q[128]|K[128]|V[128]
__device__ __align__(16) float g_denom[NMAX * HEADS]; // segment sum of exp
__device__ __align__(16) float g_agg[NMAX * OUT_F];   // un-normalized sum of exp * V
__device__ __align__(16) float g_bias[EMAX * HEADS];  // precomputed ef@We + be

// ---------------------------------------------------------------------------
// Helpers
// ---------------------------------------------------------------------------
__device__ __forceinline__ void red_add_v4(float* ptr, float x, float y, float z, float w) {
    asm volatile("red.global.add.v4.f32 [%0], {%1, %2, %3, %4};"
                 :: "l"(ptr), "f"(x), "f"(y), "f"(z), "f"(w)
                 : "memory");
}
// Packed 2x fp32 FMA: d = a*b + d (elementwise on the .lo/.hi halves).
__device__ __forceinline__ void ffma2(ull& d, ull a, ull b) {
    asm("fma.rn.f32x2 %0, %1, %2, %0;" : "+l"(d) : "l"(a), "l"(b));
}
__device__ __forceinline__ ull pack_dup(float v) {
    ull r; asm("mov.b64 %0, {%1, %1};" : "=l"(r) : "f"(v)); return r;
}
__device__ __forceinline__ ull pack2(float lo, float hi) {
    ull r; asm("mov.b64 %0, {%1, %2};" : "=l"(r) : "f"(lo), "f"(hi)); return r;
}
__device__ __forceinline__ void unpack2(ull v, float& lo, float& hi) {
    asm("mov.b64 {%0, %1}, %2;" : "=f"(lo), "=f"(hi) : "l"(v));
}

// ---------------------------------------------------------------------------
// K0: zero denom + agg (vectorized)
// ---------------------------------------------------------------------------
__global__ void init_kernel(int nMH4, int nAgg4) {
    int i = blockIdx.x * blockDim.x + threadIdx.x;
    const float4 z = make_float4(0.f, 0.f, 0.f, 0.f);
    if (i < nAgg4) ((float4*)g_agg)[i] = z;
    if (i < nMH4)  ((float4*)g_denom)[i] = z;
}

// ---------------------------------------------------------------------------
// K_bias: g_bias[e][h] = edge_features[e] @ We[:,h] + be[h]
// One thread per edge; We held as duplicated head-pairs in smem; f32x2 FMAs.
// Memory-bound: 102MB read + 25.6MB write.
// ---------------------------------------------------------------------------
__global__ __launch_bounds__(256)
void bias_kernel(const float* __restrict__ ef,
                 const float* __restrict__ We,
                 const float* __restrict__ be,
                 int nE) {
    __shared__ ull sWe2[EDGE_F * 4];  // [j][h2]: pair (We[j,2h2], We[j,2h2+1])
    __shared__ ull sbe2[4];
    if (threadIdx.x < EDGE_F * 4) {
        const int j  = threadIdx.x >> 2;
        const int h2 = threadIdx.x & 3;
        sWe2[threadIdx.x] = pack2(We[j * HEADS + 2 * h2], We[j * HEADS + 2 * h2 + 1]);
    }
    if (threadIdx.x < 4)
        sbe2[threadIdx.x] = pack2(be[2 * threadIdx.x], be[2 * threadIdx.x + 1]);
    __syncthreads();

    const int e = blockIdx.x * blockDim.x + threadIdx.x;
    if (e >= nE) return;

    ull acc[4];
#pragma unroll
    for (int h2 = 0; h2 < 4; h2++) acc[h2] = sbe2[h2];

    const float4* efp = (const float4*)(ef + (size_t)e * EDGE_F);
#pragma unroll
    for (int jq = 0; jq < 8; jq++) {
        const float4 f = efp[jq];
        const float fv[4] = {f.x, f.y, f.z, f.w};
#pragma unroll
        for (int c = 0; c < 4; c++) {
            const ull a2 = pack_dup(fv[c]);
            const ull* w = &sWe2[(4 * jq + c) * 4];
#pragma unroll
            for (int h2 = 0; h2 < 4; h2++) ffma2(acc[h2], a2, w[h2]);
        }
    }

    float o[8];
#pragma unroll
    for (int h2 = 0; h2 < 4; h2++) unpack2(acc[h2], o[2 * h2], o[2 * h2 + 1]);
    float* bp = g_bias + (size_t)e * HEADS;
    *(float4*)(bp + 0) = make_float4(o[0], o[1], o[2], o[3]);
    *(float4*)(bp + 4) = make_float4(o[4], o[5], o[6], o[7]);
}

// ---------------------------------------------------------------------------
// K1 / K3: tiled fp32 GEMM, double-buffered smem, MOV-free f32x2 mainloop.
//   C[M x 128*gridDim.y] = A[M x 128] @ B(y) + bias(y)
//   useDenom: per-head division by (g_denom + 1e-10) fused into A-tile load.
// Accumulator packs ROW-pairs: acc2[i2][j] = C(rows trow+2*i2{,+1}, col tcol+j).
//   - A operand: register pair straight out of the transposed As tile (free).
//   - B operand: pre-DUPLICATED in Bs2 (x,x,y,y,... with a 4-float pad per
//     16 to spread banks), so the dup pair comes out of LDS.128 (free).
// Per kk: 2+4 LDS.128 + 32 FFMA2, zero MOVs.
// ---------------------------------------------------------------------------
#define AS_LD 132   // padded: makes A-staging STS conflict-free
#define BS_LD 320   // 256 dup floats + 4-float pad per 16

__device__ __forceinline__ int bpad(int col2) {  // padded index in a Bs2 row
    return col2 + ((col2 >> 4) << 2);
}

__global__ __launch_bounds__(256, 2)
void sgemm_kernel(const float* __restrict__ A, int lda,
                  const float* __restrict__ W0, const float* __restrict__ W1,
                  const float* __restrict__ W2,
                  const float* __restrict__ b0, const float* __restrict__ b1,
                  const float* __restrict__ b2,
                  float* __restrict__ C, int ldc, int M,
                  int useDenom) {
    const float* B    = (blockIdx.y == 0) ? W0 : ((blockIdx.y == 1) ? W1 : W2);
    const float* bias = (blockIdx.y == 0) ? b0 : ((blockIdx.y == 1) ? b1 : b2);

    __shared__ float As[2][8][AS_LD];    // [buf][k][m] transposed
    __shared__ float Bs2[2][8][BS_LD];   // [buf][k][padded dup cols]

    const int tid     = threadIdx.x;
    const int rowBase = blockIdx.x * 128;
    const int colBase = blockIdx.y * 128;

    const int trow = (tid / 16) * 8;
    const int tcol = (tid % 16) * 8;
    const int m16  = tid % 16;

    const int aRow = tid >> 1;
    const int aCol = (tid & 1) * 4;
    const int bRow = tid >> 5;
    const int bCol = (tid & 31) * 4;
    const int bP   = bpad(2 * bCol);

    const int  gr   = rowBase + aRow;
    const bool aOk  = (gr < M);
    const float* aPtr = A + (size_t)gr * lda + aCol;
    const float* bPtr = B + (size_t)bRow * 128 + bCol;

    ull acc2[4][8];
#pragma unroll
    for (int i = 0; i < 4; i++)
#pragma unroll
        for (int j = 0; j < 8; j++) acc2[i][j] = 0ull;

    // ---- prologue: tile 0 -> buffer 0 ----
    float4 av = make_float4(0.f, 0.f, 0.f, 0.f);
    if (aOk) {
        av = *(const float4*)(aPtr);
        if (useDenom) {
            const float d   = g_denom[(size_t)gr * HEADS + (aCol >> 4)] + 1e-10f;
            const float inv = __fdividef(1.0f, d);
            av.x *= inv; av.y *= inv; av.z *= inv; av.w *= inv;
        }
    }
    float4 bv = *(const float4*)(bPtr);

    As[0][aCol + 0][aRow] = av.x;
    As[0][aCol + 1][aRow] = av.y;
    As[0][aCol + 2][aRow] = av.z;
    As[0][aCol + 3][aRow] = av.w;
    *(float4*)&Bs2[0][bRow][bP]     = make_float4(bv.x, bv.x, bv.y, bv.y);
    *(float4*)&Bs2[0][bRow][bP + 4] = make_float4(bv.z, bv.z, bv.w, bv.w);
    __syncthreads();

#pragma unroll 1
    for (int it = 0; it < 16; it++) {
        const int cur = it & 1;

        // ---- prefetch next tile into registers ----
        float4 avn, bvn;
        if (it < 15) {
            const int k0n = (it + 1) * 8;
            avn = make_float4(0.f, 0.f, 0.f, 0.f);
            if (aOk) {
                avn = *(const float4*)(aPtr + k0n);
                if (useDenom) {
                    const float d   = g_denom[(size_t)gr * HEADS + ((k0n + aCol) >> 4)] + 1e-10f;
                    const float inv = __fdividef(1.0f, d);
                    avn.x *= inv; avn.y *= inv; avn.z *= inv; avn.w *= inv;
                }
            }
            bvn = *(const float4*)(bPtr + (size_t)k0n * 128);
        }

        // ---- compute on current buffer: MOV-free f32x2 ----
#pragma unroll
        for (int kk = 0; kk < 8; kk++) {
            const float4 a0 = *(const float4*)&As[cur][kk][trow];
            const float4 a1 = *(const float4*)&As[cur][kk][trow + 4];
            const float4 d0 = *(const float4*)&Bs2[cur][kk][20 * m16];
            const float4 d1 = *(const float4*)&Bs2[cur][kk][20 * m16 + 4];
            const float4 d2 = *(const float4*)&Bs2[cur][kk][20 * m16 + 8];
            const float4 d3 = *(const float4*)&Bs2[cur][kk][20 * m16 + 12];

            ull ap[4], bq[8];
            ap[0] = *(const ull*)&a0.x;  ap[1] = *(const ull*)&a0.z;
            ap[2] = *(const ull*)&a1.x;  ap[3] = *(const ull*)&a1.z;
            bq[0] = *(const ull*)&d0.x;  bq[1] = *(const ull*)&d0.z;
            bq[2] = *(const ull*)&d1.x;  bq[3] = *(const ull*)&d1.z;
            bq[4] = *(const ull*)&d2.x;  bq[5] = *(const ull*)&d2.z;
            bq[6] = *(const ull*)&d3.x;  bq[7] = *(const ull*)&d3.z;

#pragma unroll
            for (int i2 = 0; i2 < 4; i2++)
#pragma unroll
                for (int j = 0; j < 8; j++)
                    ffma2(acc2[i2][j], ap[i2], bq[j]);
        }

        // ---- stage next tile into the other buffer ----
        if (it < 15) {
            const int nxt = cur ^ 1;
            As[nxt][aCol + 0][aRow] = avn.x;
            As[nxt][aCol + 1][aRow] = avn.y;
            As[nxt][aCol + 2][aRow] = avn.z;
            As[nxt][aCol + 3][aRow] = avn.w;
            *(float4*)&Bs2[nxt][bRow][bP]     = make_float4(bvn.x, bvn.x, bvn.y, bvn.y);
            *(float4*)&Bs2[nxt][bRow][bP + 4] = make_float4(bvn.z, bvn.z, bvn.w, bvn.w);
        }
        __syncthreads();
    }

    // --- epilogue: add bias, store (row pairs) ---
    float bb[8];
#pragma unroll
    for (int j = 0; j < 8; j++) bb[j] = bias[tcol + j];

#pragma unroll
    for (int i2 = 0; i2 < 4; i2++) {
        float lo[8], hi[8];
#pragma unroll
        for (int j = 0; j < 8; j++) unpack2(acc2[i2][j], lo[j], hi[j]);

        const int r0 = rowBase + trow + 2 * i2;
        if (r0 < M) {
            float* cp = C + (size_t)r0 * ldc + colBase + tcol;
            *(float4*)(cp + 0) = make_float4(lo[0] + bb[0], lo[1] + bb[1], lo[2] + bb[2], lo[3] + bb[3]);
            *(float4*)(cp + 4) = make_float4(lo[4] + bb[4], lo[5] + bb[5], lo[6] + bb[6], lo[7] + bb[7]);
        }
        if (r0 + 1 < M) {
            float* cp = C + (size_t)(r0 + 1) * ldc + colBase + tcol;
            *(float4*)(cp + 0) = make_float4(hi[0] + bb[0], hi[1] + bb[1], hi[2] + bb[2], hi[3] + bb[3]);
            *(float4*)(cp + 4) = make_float4(hi[4] + bb[4], hi[5] + bb[5], hi[6] + bb[6], hi[7] + bb[7]);
        }
    }
}

// ---------------------------------------------------------------------------
// K2 (fused): per-(edge, head): p = exp(0.25*<Q[tgt,h],K[src,h]> + bias[e,h]);
// denom[tgt,h] += p;  agg[tgt,h*16:+16] += p * V[src,h*16:+16].
// Segment-max dropped (scores bounded, softmax shift-invariant).
// ---------------------------------------------------------------------------
__global__ __launch_bounds__(256)
void edge_fused_kernel(const int* __restrict__ ei, int nE) {
    const int gtid = blockIdx.x * blockDim.x + threadIdx.x;
    if (gtid >= nE * HEADS) return;
    const int e = gtid >> 3;
    const int h = gtid & 7;

    const int src = ei[e];
    const int tgt = ei[nE + e];

    // Q[tgt,h] . K[src,h]  (each group-of-8 threads covers a 512B row)
    const float4* qp = (const float4*)(g_QKV + (size_t)tgt * 384 + h * HDIM);
    const float4* kp = (const float4*)(g_QKV + (size_t)src * 384 + 128 + h * HDIM);
    float dot = 0.0f;
#pragma unroll
    for (int i = 0; i < 4; i++) {
        const float4 q = qp[i];
        const float4 k = kp[i];
        dot += q.x * k.x + q.y * k.y + q.z * k.z + q.w * k.w;
    }

    const float p = __expf(dot * 0.25f + g_bias[gtid]);   // scale = HDIM^-0.5

    atomicAdd(&g_denom[(size_t)tgt * HEADS + h], p);

    const float4* vp = (const float4*)(g_QKV + (size_t)src * 384 + 256 + h * HDIM);
    float* op = g_agg + (size_t)tgt * OUT_F + h * HDIM;
#pragma unroll
    for (int i = 0; i < 4; i++) {
        const float4 v = vp[i];
        red_add_v4(op + i * 4, p * v.x, p * v.y, p * v.z, p * v.w);
    }
}

// ---------------------------------------------------------------------------
// Launch
// ---------------------------------------------------------------------------
extern "C" void kernel_launch(void* const* d_in, const int* in_sizes, int n_in,
                              void* d_out, int out_size) {
    const float* X  = (const float*)d_in[0];
    const int*   EI = (const int*)d_in[1];        // int64 in reference -> int32 here
    const float* EF = (const float*)d_in[2];
    const float* Wq = (const float*)d_in[3];
    const float* bq = (const float*)d_in[4];
    const float* Wk = (const float*)d_in[5];
    const float* bk = (const float*)d_in[6];
    const float* Wv = (const float*)d_in[7];
    const float* bv = (const float*)d_in[8];
    const float* We = (const float*)d_in[9];
    const float* be = (const float*)d_in[10];
    const float* Wo = (const float*)d_in[11];
    const float* bo = (const float*)d_in[12];
    float* OUT = (float*)d_out;

    int M  = in_sizes[0] / IN_F;   // 50000
    int nE = in_sizes[1] / 2;      // 800000
    if (M > NMAX)  M = NMAX;
    if (nE > EMAX) nE = EMAX;

    const int nMH4  = (M * HEADS) / 4;
    const int nAgg4 = (M * OUT_F) / 4;
    const int nEH   = nE * HEADS;

    float* pQKV = nullptr;
    float* pAgg = nullptr;
    cudaGetSymbolAddress((void**)&pQKV, g_QKV);
    cudaGetSymbolAddress((void**)&pAgg, g_agg);

    // K0: zero denom + agg
    init_kernel<<<(nAgg4 + 255) / 256, 256>>>(nMH4, nAgg4);

    // K_bias: precompute per-(edge, head) bias
    bias_kernel<<<(nE + 255) / 256, 256>>>(EF, We, be, nE);

    // K1: fused QKV projection -> g_QKV (node-major interleaved Q|K|V)
    const int mb = (M + 127) / 128;
    sgemm_kernel<<<dim3(mb, 3), 256>>>(X, IN_F,
                                       Wq, Wk, Wv, bq, bk, bv,
                                       pQKV, 384, M, /*useDenom=*/0);

    // K2: fused edge logits + exp + denom + weighted-V scatter
    edge_fused_kernel<<<(nEH + 255) / 256, 256>>>(EI, nE);

    // K3: normalize (fused into A-load) + output projection -> d_out
    sgemm_kernel<<<dim3(mb, 1), 256>>>(pAgg, OUT_F,
                                       Wo, Wo, Wo, bo, bo, bo,
                                       OUT, OUT_F, M, /*useDenom=*/1);
}